// round 1
// baseline (speedup 1.0000x reference)
#include <cuda_runtime.h>
#include <cstdint>

#define N_NODES 100000
#define N_EDGES 3200000
#define FEAT 64
#define OUT_DIM 2

// Folded weights: W1 = W_rel @ W_pred, W2 = W_root @ W_pred  (both [64][2])
// bias = b_rel @ W_pred + b_pred  ([2])
__device__ float g_W1[FEAT][OUT_DIM];
__device__ float g_W2[FEAT][OUT_DIM];
__device__ float g_bias[OUT_DIM];

// Per-node projected message m = h @ W1  (L2-resident: 800 KB)
__device__ float2 g_m[N_NODES];

// ---------------------------------------------------------------------------
// Kernel A: fold the weight matrices (tiny, one block)
// ---------------------------------------------------------------------------
__global__ void fold_weights_kernel(const float* __restrict__ W_rel,
                                    const float* __restrict__ b_rel,
                                    const float* __restrict__ W_root,
                                    const float* __restrict__ W_pred,
                                    const float* __restrict__ b_pred) {
    int t = threadIdx.x;           // 128 threads
    int k = t >> 1;                // 0..63
    int o = t & 1;                 // 0..1
    float s1 = 0.f, s2 = 0.f;
    #pragma unroll
    for (int j = 0; j < FEAT; ++j) {
        float wp = W_pred[j * OUT_DIM + o];
        s1 += W_rel[k * FEAT + j] * wp;
        s2 += W_root[k * FEAT + j] * wp;
    }
    g_W1[k][o] = s1;
    g_W2[k][o] = s2;
    if (t < OUT_DIM) {
        float b = 0.f;
        #pragma unroll
        for (int j = 0; j < FEAT; ++j) b += b_rel[j] * W_pred[j * OUT_DIM + t];
        g_bias[t] = b + b_pred[t];
    }
}

// ---------------------------------------------------------------------------
// Kernel B: one warp per node.
//   m[i]   = h[i] @ W1                     (stored to g_m)
//   out[i] = h[i] @ W2 + bias              (root term initializes output)
// h[i] = [pos[i,0:32], vel[i,0:32]]; lane l owns feature l (pos) and 32+l (vel).
// ---------------------------------------------------------------------------
__global__ void node_kernel(const float* __restrict__ pos,
                            const float* __restrict__ vel,
                            float* __restrict__ out) {
    int gwarp = (blockIdx.x * blockDim.x + threadIdx.x) >> 5;
    int lane  = threadIdx.x & 31;
    if (gwarp >= N_NODES) return;

    float p = pos[gwarp * 32 + lane];   // coalesced 128B per warp
    float v = vel[gwarp * 32 + lane];

    float m0 = p * g_W1[lane][0] + v * g_W1[32 + lane][0];
    float m1 = p * g_W1[lane][1] + v * g_W1[32 + lane][1];
    float r0 = p * g_W2[lane][0] + v * g_W2[32 + lane][0];
    float r1 = p * g_W2[lane][1] + v * g_W2[32 + lane][1];

    #pragma unroll
    for (int off = 16; off > 0; off >>= 1) {
        m0 += __shfl_xor_sync(0xffffffffu, m0, off);
        m1 += __shfl_xor_sync(0xffffffffu, m1, off);
        r0 += __shfl_xor_sync(0xffffffffu, r0, off);
        r1 += __shfl_xor_sync(0xffffffffu, r1, off);
    }
    if (lane == 0) {
        g_m[gwarp] = make_float2(m0, m1);
        out[2 * gwarp + 0] = r0 + g_bias[0];
        out[2 * gwarp + 1] = r1 + g_bias[1];
    }
}

// ---------------------------------------------------------------------------
// Kernel C: one thread per edge. out[dst] += m[src] via vector RED (L2 atomics).
// m (800 KB) and out (800 KB) are both L2-resident; only the edge-index
// stream (25.6 MB) hits DRAM.
// ---------------------------------------------------------------------------
__global__ void edge_kernel(const int* __restrict__ src,
                            const int* __restrict__ dst,
                            float* __restrict__ out) {
    int e = blockIdx.x * blockDim.x + threadIdx.x;
    if (e >= N_EDGES) return;
    int s = src[e];
    int d = dst[e];
    float2 mm = g_m[s];
    // single vector reduction: halves the RED instruction count vs 2x atomicAdd
    asm volatile("red.global.add.v2.f32 [%0], {%1, %2};"
                 :: "l"(out + 2 * d), "f"(mm.x), "f"(mm.y)
                 : "memory");
}

// ---------------------------------------------------------------------------
// Launch
// Inputs (metadata order): pos, vel, edge_index, W_rel, b_rel, W_root, W_pred, b_pred
// ---------------------------------------------------------------------------
extern "C" void kernel_launch(void* const* d_in, const int* in_sizes, int n_in,
                              void* d_out, int out_size) {
    const float* pos    = (const float*)d_in[0];
    const float* vel    = (const float*)d_in[1];
    const int*   eidx   = (const int*)  d_in[2];
    const float* W_rel  = (const float*)d_in[3];
    const float* b_rel  = (const float*)d_in[4];
    const float* W_root = (const float*)d_in[5];
    const float* W_pred = (const float*)d_in[6];
    const float* b_pred = (const float*)d_in[7];
    float* out = (float*)d_out;

    const int n_edges = in_sizes[2] / 2;          // 3.2M
    const int* src = eidx;
    const int* dst = eidx + n_edges;

    fold_weights_kernel<<<1, 128>>>(W_rel, b_rel, W_root, W_pred, b_pred);

    // warp per node: 8 warps/block * 12500 blocks = 100000 warps
    node_kernel<<<(N_NODES * 32 + 255) / 256, 256>>>(pos, vel, out);

    edge_kernel<<<(N_EDGES + 255) / 256, 256>>>(src, dst, out);
}

// round 2
// speedup vs baseline: 1.0878x; 1.0878x over previous
#include <cuda_runtime.h>
#include <cstdint>

#define N_NODES 100000
#define FEAT 64
#define OUT_DIM 2

// Folded weights: W1 = W_rel @ W_pred, W2 = W_root @ W_pred  (both [64][2])
// bias = b_rel @ W_pred + b_pred  ([2])
__device__ float g_W1[FEAT][OUT_DIM];
__device__ float g_W2[FEAT][OUT_DIM];
__device__ float g_bias[OUT_DIM];

// Per-node projected message m = h @ W1  (L2-resident: 800 KB)
__device__ float2 g_m[N_NODES];

// ---------------------------------------------------------------------------
// Kernel A: fold weights. One warp per output element (128 warps total).
// Each lane handles 2 of the 64 dot-product terms, butterfly-reduced.
// ---------------------------------------------------------------------------
__global__ void fold_weights_kernel(const float* __restrict__ W_rel,
                                    const float* __restrict__ b_rel,
                                    const float* __restrict__ W_root,
                                    const float* __restrict__ W_pred,
                                    const float* __restrict__ b_pred) {
    int w    = (blockIdx.x * blockDim.x + threadIdx.x) >> 5;  // 0..127
    int lane = threadIdx.x & 31;
    if (w >= FEAT * OUT_DIM) return;
    int k = w >> 1;        // 0..63  (row of W1/W2)
    int o = w & 1;         // 0..1   (output col)
    int j0 = lane, j1 = lane + 32;

    float wp0 = W_pred[j0 * OUT_DIM + o];
    float wp1 = W_pred[j1 * OUT_DIM + o];
    float s1 = W_rel [k * FEAT + j0] * wp0 + W_rel [k * FEAT + j1] * wp1;
    float s2 = W_root[k * FEAT + j0] * wp0 + W_root[k * FEAT + j1] * wp1;
    // bias: only warps 0 and 1 (k==0, o==w) compute it
    float bb = (w < OUT_DIM) ? (b_rel[j0] * wp0 + b_rel[j1] * wp1) : 0.f;

    #pragma unroll
    for (int off = 16; off > 0; off >>= 1) {
        s1 += __shfl_xor_sync(0xffffffffu, s1, off);
        s2 += __shfl_xor_sync(0xffffffffu, s2, off);
        bb += __shfl_xor_sync(0xffffffffu, bb, off);
    }
    if (lane == 0) {
        g_W1[k][o] = s1;
        g_W2[k][o] = s2;
        if (w < OUT_DIM) g_bias[w] = bb + b_pred[w];
    }
}

// ---------------------------------------------------------------------------
// Kernel B: one warp per node.
//   m[i]   = h[i] @ W1                     (stored to g_m)
//   out[i] = h[i] @ W2 + bias              (root term initializes output)
// h[i] = [pos[i,0:32], vel[i,0:32]]; lane l owns feature l (pos) and 32+l (vel).
// ---------------------------------------------------------------------------
__global__ void node_kernel(const float* __restrict__ pos,
                            const float* __restrict__ vel,
                            float* __restrict__ out) {
    int gwarp = (blockIdx.x * blockDim.x + threadIdx.x) >> 5;
    int lane  = threadIdx.x & 31;
    if (gwarp >= N_NODES) return;

    float p = __ldcs(pos + gwarp * 32 + lane);   // streaming: read-once data
    float v = __ldcs(vel + gwarp * 32 + lane);

    float m0 = p * g_W1[lane][0] + v * g_W1[32 + lane][0];
    float m1 = p * g_W1[lane][1] + v * g_W1[32 + lane][1];
    float r0 = p * g_W2[lane][0] + v * g_W2[32 + lane][0];
    float r1 = p * g_W2[lane][1] + v * g_W2[32 + lane][1];

    #pragma unroll
    for (int off = 16; off > 0; off >>= 1) {
        m0 += __shfl_xor_sync(0xffffffffu, m0, off);
        m1 += __shfl_xor_sync(0xffffffffu, m1, off);
        r0 += __shfl_xor_sync(0xffffffffu, r0, off);
        r1 += __shfl_xor_sync(0xffffffffu, r1, off);
    }
    if (lane == 0) {
        g_m[gwarp] = make_float2(m0, m1);
        out[2 * gwarp + 0] = r0 + g_bias[0];
        out[2 * gwarp + 1] = r1 + g_bias[1];
    }
}

// ---------------------------------------------------------------------------
// Kernel C: 4 edges per thread. out[dst] += m[src] via vector RED (L2 atomics).
// int4 index loads with streaming hint (25.6 MB edge stream shouldn't evict
// the L2-resident m/out arrays); m gathers + REDs stay in L2.
// ---------------------------------------------------------------------------
__device__ __forceinline__ void red_v2(float* addr, float2 v) {
    asm volatile("red.global.add.v2.f32 [%0], {%1, %2};"
                 :: "l"(addr), "f"(v.x), "f"(v.y) : "memory");
}

__global__ void edge_kernel(const int* __restrict__ src,
                            const int* __restrict__ dst,
                            float* __restrict__ out,
                            int n_edges) {
    int t = blockIdx.x * blockDim.x + threadIdx.x;
    int base = t * 4;
    if (base + 3 < n_edges) {
        int4 s = __ldcs((const int4*)(src + base));
        int4 d = __ldcs((const int4*)(dst + base));
        float2 a = g_m[s.x];
        float2 b = g_m[s.y];
        float2 c = g_m[s.z];
        float2 e = g_m[s.w];
        red_v2(out + 2 * d.x, a);
        red_v2(out + 2 * d.y, b);
        red_v2(out + 2 * d.z, c);
        red_v2(out + 2 * d.w, e);
    } else {
        for (int i = base; i < n_edges; ++i) {
            float2 mm = g_m[src[i]];
            red_v2(out + 2 * dst[i], mm);
        }
    }
}

// ---------------------------------------------------------------------------
// Launch
// Inputs (metadata order): pos, vel, edge_index, W_rel, b_rel, W_root, W_pred, b_pred
// ---------------------------------------------------------------------------
extern "C" void kernel_launch(void* const* d_in, const int* in_sizes, int n_in,
                              void* d_out, int out_size) {
    const float* pos    = (const float*)d_in[0];
    const float* vel    = (const float*)d_in[1];
    const int*   eidx   = (const int*)  d_in[2];
    const float* W_rel  = (const float*)d_in[3];
    const float* b_rel  = (const float*)d_in[4];
    const float* W_root = (const float*)d_in[5];
    const float* W_pred = (const float*)d_in[6];
    const float* b_pred = (const float*)d_in[7];
    float* out = (float*)d_out;

    const int n_edges = in_sizes[2] / 2;          // 3.2M
    const int* src = eidx;
    const int* dst = eidx + n_edges;

    fold_weights_kernel<<<4, 1024>>>(W_rel, b_rel, W_root, W_pred, b_pred);

    node_kernel<<<(N_NODES * 32 + 1023) / 1024, 1024>>>(pos, vel, out);

    int n_thr = (n_edges + 3) / 4;
    edge_kernel<<<(n_thr + 255) / 256, 256>>>(src, dst, out, n_edges);
}